// round 1
// baseline (speedup 1.0000x reference)
#include <cuda_runtime.h>

// Problem dims
#define N_   128
#define C_   64
#define T_   288
#define V_   16
#define S_   3
#define IC_  16
#define KCT  (IC_*T_)      // 4608

// Kernel 1 tiling
#define TT1  8
#define J1   (TT1*V_)      // 128
#define NCH  (T_/TT1)      // 36
#define RS1  132           // padded row stride (floats), mult of 4

// Kernel 3 tiling
#define TT3  16
#define J3   (TT3*V_)      // 256
#define NCH3 (T_/TT3)      // 18
#define RS3  258           // padded row stride (floats), even for u64 loads

// Scratch (no cudaMalloc allowed)
__device__ float g_partial[(long)N_*NCH*S_*V_*V_];   // [n][ch][s][v*16+w]
__device__ float g_att[(long)N_*S_*V_*V_];           // [n][s][v*16+w]

typedef unsigned long long u64;

__device__ __forceinline__ u64 splat2(float x) {
    u64 r; asm("mov.b64 %0, {%1, %1};" : "=l"(r) : "f"(x)); return r;
}
__device__ __forceinline__ void fma2(u64& d, u64 a, u64 b) {
    asm("fma.rn.f32x2 %0, %1, %2, %0;" : "+l"(d) : "l"(a), "l"(b));
}
__device__ __forceinline__ u64 add2(u64 a, u64 b) {
    u64 r; asm("add.rn.f32x2 %0, %1, %2;" : "=l"(r) : "l"(a), "l"(b)); return r;
}
__device__ __forceinline__ float2 unpack2(u64 a) {
    float2 r; asm("mov.b64 {%0, %1}, %2;" : "=f"(r.x), "=f"(r.y) : "l"(a)); return r;
}

// ---------------------------------------------------------------------------
// Kernel 1: att logit partials.
// Grid (NCH, N). 256 threads. For one (n, t-chunk): stage x tile [64][128],
// per subset s compute fa/fb tiles [16][128] (fa = Wa x + ba), then
// partial[v][w] = sum_{i,t'} fa[i][t'*16+v] * fb[i][t'*16+w].
// ---------------------------------------------------------------------------
#define SM1_XS   0
#define SM1_FA   (SM1_XS + 64*RS1)            // 8448
#define SM1_FB   (SM1_FA + 16*RS1)            // 10560
#define SM1_WAT  (SM1_FB + 16*RS1)            // 12672
#define SM1_WBT  (SM1_WAT + S_*64*16)         // 15744
#define SM1_ATTP (SM1_WBT + S_*64*16)         // 18816
#define SM1_FLOATS (SM1_ATTP + 4*256)         // 19840
#define SMEM1_BYTES (SM1_FLOATS*4)

extern "C" __global__ void __launch_bounds__(256, 2)
k1_att_partial(const float* __restrict__ x,
               const float* __restrict__ Wa, const float* __restrict__ ba,
               const float* __restrict__ Wb, const float* __restrict__ bb)
{
    extern __shared__ float sm[];
    float* xs   = sm + SM1_XS;    // [64][RS1]
    float* fas  = sm + SM1_FA;    // [16][RS1]
    float* fbs  = sm + SM1_FB;    // [16][RS1]
    float* Wat  = sm + SM1_WAT;   // [s][c][i]
    float* Wbt  = sm + SM1_WBT;   // [s][c][i]
    float* attp = sm + SM1_ATTP;  // [4][256]

    const int ch  = blockIdx.x;
    const int n   = blockIdx.y;
    const int tid = threadIdx.x;
    const int t0  = ch * TT1;

    // Stage x tile (contiguous 128 floats per channel row)
    const long xbase = (long)n*C_*T_*V_ + (long)t0*V_;
    for (int idx = tid; idx < C_*J1; idx += 256) {
        int c = idx >> 7, j = idx & 127;
        xs[c*RS1 + j] = x[xbase + (long)c*(T_*V_) + j];
    }
    // Stage W^T: Wat[s][c][i] = Wa[s][i][c]
    for (int idx = tid; idx < S_*IC_*C_; idx += 256) {
        int i = idx & 15, c = (idx >> 4) & 63, s = idx >> 10;
        Wat[(s*64 + c)*16 + i] = Wa[(s*16 + i)*64 + c];
        Wbt[(s*64 + c)*16 + i] = Wb[(s*16 + i)*64 + c];
    }
    __syncthreads();

    // phase-1 mapping: 2 i x 4 j per thread
    const int ib = tid >> 5, jb = tid & 31;
    const int i0 = ib*2, j0 = jb*4;
    // phase-2 mapping: 2 v x 2 w per thread, 4-way split over terms
    const int q   = tid >> 6;
    const int pvb = (tid >> 3) & 7;
    const int pwb = tid & 7;

    for (int s = 0; s < S_; s++) {
        // ---- phase 1: fa/fb tiles ----
        float aA[2][4], aB[2][4];
        #pragma unroll
        for (int ii = 0; ii < 2; ii++)
            #pragma unroll
            for (int qq = 0; qq < 4; qq++) { aA[ii][qq] = 0.f; aB[ii][qq] = 0.f; }

        const float* wap = &Wat[s*64*16];
        const float* wbp = &Wbt[s*64*16];
        #pragma unroll 4
        for (int c = 0; c < 64; c++) {
            float4 xv = *(const float4*)&xs[c*RS1 + j0];
            float xa[4] = {xv.x, xv.y, xv.z, xv.w};
            #pragma unroll
            for (int ii = 0; ii < 2; ii++) {
                float wav = wap[c*16 + i0 + ii];
                float wbv = wbp[c*16 + i0 + ii];
                #pragma unroll
                for (int qq = 0; qq < 4; qq++) {
                    aA[ii][qq] += wav * xa[qq];
                    aB[ii][qq] += wbv * xa[qq];
                }
            }
        }
        #pragma unroll
        for (int ii = 0; ii < 2; ii++) {
            float bav = ba[s*16 + i0 + ii];
            float bbv = bb[s*16 + i0 + ii];
            float4 fa4 = make_float4(aA[ii][0]+bav, aA[ii][1]+bav, aA[ii][2]+bav, aA[ii][3]+bav);
            float4 fb4 = make_float4(aB[ii][0]+bbv, aB[ii][1]+bbv, aB[ii][2]+bbv, aB[ii][3]+bbv);
            *(float4*)&fas[(i0+ii)*RS1 + j0] = fa4;
            *(float4*)&fbs[(i0+ii)*RS1 + j0] = fb4;
        }
        __syncthreads();

        // ---- phase 2: att partial, 2x2 (v,w) tile, terms split 4 ways ----
        float a00 = 0.f, a01 = 0.f, a10 = 0.f, a11 = 0.f;
        #pragma unroll 8
        for (int r = 0; r < 32; r++) {
            int term = q*32 + r;
            int i  = term >> 3;
            int tp = term & 7;
            const float* fr = &fas[i*RS1 + tp*16];
            const float* gr = &fbs[i*RS1 + tp*16];
            float f0 = fr[2*pvb], f1 = fr[2*pvb + 1];
            float g0 = gr[2*pwb], g1 = gr[2*pwb + 1];
            a00 += f0*g0; a01 += f0*g1; a10 += f1*g0; a11 += f1*g1;
        }
        attp[q*256 + (2*pvb  )*16 + 2*pwb    ] = a00;
        attp[q*256 + (2*pvb  )*16 + 2*pwb + 1] = a01;
        attp[q*256 + (2*pvb+1)*16 + 2*pwb    ] = a10;
        attp[q*256 + (2*pvb+1)*16 + 2*pwb + 1] = a11;
        __syncthreads();

        float red = attp[tid] + attp[256 + tid] + attp[512 + tid] + attp[768 + tid];
        g_partial[(((long)n*NCH + ch)*S_ + s)*256 + tid] = red;
        // next-iteration syncs protect attp/fas reuse
    }
}

// ---------------------------------------------------------------------------
// Kernel 2: reduce chunks, /K, softmax over v, + (A_base + PA).
// Grid N*S blocks, 256 threads (one per (v,w)).
// ---------------------------------------------------------------------------
extern "C" __global__ void k2_softmax(const float* __restrict__ Abase,
                                      const float* __restrict__ PA)
{
    const int b = blockIdx.x;          // n*3 + s
    const int n = b / S_, s = b % S_;
    const int tid = threadIdx.x;       // v*16 + w
    const int w = tid & 15;

    __shared__ float sv[256];
    __shared__ float se[256];

    float sum = 0.f;
    const float* p = &g_partial[((long)n*NCH)*S_*256 + s*256 + tid];
    for (int chv = 0; chv < NCH; chv++) sum += p[(long)chv * (S_*256)];
    float val = sum * (1.0f / (float)KCT);

    sv[tid] = val;
    __syncthreads();
    float m = -1e30f;
    #pragma unroll
    for (int vv = 0; vv < 16; vv++) m = fmaxf(m, sv[vv*16 + w]);
    float e = expf(val - m);
    se[tid] = e;
    __syncthreads();
    float ss = 0.f;
    #pragma unroll
    for (int vv = 0; vv < 16; vv++) ss += se[vv*16 + w];

    float a = e / ss + Abase[s*256 + tid] + PA[s*256 + tid];
    g_att[(long)b*256 + tid] = a;
}

// ---------------------------------------------------------------------------
// Kernel 3: z = x @ att, y = sum_s Wd_s @ z_s, BN + bias + residual.
// Grid (NCH3, N), 512 threads. Packed f32x2 FMA throughout the hot loops.
// ---------------------------------------------------------------------------
#define SM3_XS   0
#define SM3_ZS   (SM3_XS + 64*RS3)            // 16512
#define SM3_WDT  (SM3_ZS + 64*RS3)            // 33024
#define SM3_ATT  (SM3_WDT + S_*64*64)         // 45312
#define SM3_FLOATS (SM3_ATT + S_*256)         // 46080
#define SMEM3_BYTES (SM3_FLOATS*4)

extern "C" __global__ void __launch_bounds__(512, 1)
k3_out(const float* __restrict__ x,  const float* __restrict__ Wd,
       const float* __restrict__ bd, const float* __restrict__ gamma,
       const float* __restrict__ beta, float* __restrict__ out)
{
    extern __shared__ float sm[];
    float* xs   = sm + SM3_XS;    // [64][RS3]
    float* zs   = sm + SM3_ZS;    // [64][RS3]
    float* Wdt  = sm + SM3_WDT;   // [s][c][o]
    float* atts = sm + SM3_ATT;   // [s][v][w]

    const int ch  = blockIdx.x;
    const int n   = blockIdx.y;
    const int tid = threadIdx.x;
    const int t0  = ch * TT3;

    const long xbase = (long)n*C_*T_*V_ + (long)t0*V_;
    for (int idx = tid; idx < C_*J3; idx += 512) {
        int c = idx >> 8, j = idx & 255;
        xs[c*RS3 + j] = x[xbase + (long)c*(T_*V_) + j];
    }
    for (int idx = tid; idx < S_*C_*C_; idx += 512) {
        int o = idx & 63, c = (idx >> 6) & 63, s = idx >> 12;
        Wdt[(s*64 + c)*64 + o] = Wd[(s*64 + o)*64 + c];
    }
    for (int idx = tid; idx < S_*256; idx += 512)
        atts[idx] = g_att[(long)n*S_*256 + idx];
    __syncthreads();

    // y mapping: 4 o x 8 j (two float4 j-groups, 128 apart)
    const int ob = tid >> 5, jbv = tid & 31;
    const int o0 = ob*4, jA = jbv*4, jB = 128 + jbv*4;
    u64 yacc[16];
    #pragma unroll
    for (int k = 0; k < 16; k++) yacc[k] = 0ull;

    // z mapping: 2 c x 16 j (one t' group)
    const int tb = tid >> 5, cb = tid & 31;
    const int c0 = cb*2, jz = tb*16;

    for (int s = 0; s < S_; s++) {
        // ---- z tile ----
        u64 zacc[16];
        #pragma unroll
        for (int k = 0; k < 16; k++) zacc[k] = 0ull;
        const float* ap = &atts[s*256];
        #pragma unroll
        for (int v = 0; v < 16; v++) {
            u64 ar[8];
            #pragma unroll
            for (int p = 0; p < 8; p++)
                ar[p] = *(const u64*)&ap[v*16 + 2*p];
            u64 x0 = splat2(xs[ c0     *RS3 + jz + v]);
            u64 x1 = splat2(xs[(c0 + 1)*RS3 + jz + v]);
            #pragma unroll
            for (int p = 0; p < 8; p++) {
                fma2(zacc[p],     x0, ar[p]);
                fma2(zacc[8 + p], x1, ar[p]);
            }
        }
        #pragma unroll
        for (int p = 0; p < 8; p++) {
            *(u64*)&zs[ c0     *RS3 + jz + 2*p] = zacc[p];
            *(u64*)&zs[(c0 + 1)*RS3 + jz + 2*p] = zacc[8 + p];
        }
        __syncthreads();

        // ---- y += Wd_s @ z_s ----
        const float* wp = &Wdt[s*64*64];
        #pragma unroll 4
        for (int c = 0; c < 64; c++) {
            float4 w4 = *(const float4*)&wp[c*64 + o0];
            u64 w0 = splat2(w4.x), w1 = splat2(w4.y);
            u64 w2 = splat2(w4.z), w3 = splat2(w4.w);
            const float* zr = &zs[c*RS3];
            u64 z0 = *(const u64*)&zr[jA];
            u64 z1 = *(const u64*)&zr[jA + 2];
            u64 z2 = *(const u64*)&zr[jB];
            u64 z3 = *(const u64*)&zr[jB + 2];
            fma2(yacc[ 0], w0, z0); fma2(yacc[ 1], w0, z1);
            fma2(yacc[ 2], w0, z2); fma2(yacc[ 3], w0, z3);
            fma2(yacc[ 4], w1, z0); fma2(yacc[ 5], w1, z1);
            fma2(yacc[ 6], w1, z2); fma2(yacc[ 7], w1, z3);
            fma2(yacc[ 8], w2, z0); fma2(yacc[ 9], w2, z1);
            fma2(yacc[10], w2, z2); fma2(yacc[11], w2, z3);
            fma2(yacc[12], w3, z0); fma2(yacc[13], w3, z1);
            fma2(yacc[14], w3, z2); fma2(yacc[15], w3, z3);
        }
        __syncthreads();
    }

    // ---- epilogue: BN scale/shift + bd sum + residual ----
    const float rsv = rsqrtf(1.0f + 1e-5f);
    const long obase = (long)n*C_*T_*V_ + (long)t0*V_;
    #pragma unroll
    for (int oo = 0; oo < 4; oo++) {
        int o = o0 + oo;
        float sc = gamma[o] * rsv;
        float bi = beta[o] + bd[o] + bd[64 + o] + bd[128 + o];
        u64 sc2 = splat2(sc), bi2 = splat2(bi);

        u64 r0 = bi2, r1 = bi2, r2 = bi2, r3 = bi2;
        fma2(r0, yacc[oo*4 + 0], sc2);
        fma2(r1, yacc[oo*4 + 1], sc2);
        fma2(r2, yacc[oo*4 + 2], sc2);
        fma2(r3, yacc[oo*4 + 3], sc2);

        r0 = add2(r0, *(const u64*)&xs[o*RS3 + jA]);
        r1 = add2(r1, *(const u64*)&xs[o*RS3 + jA + 2]);
        r2 = add2(r2, *(const u64*)&xs[o*RS3 + jB]);
        r3 = add2(r3, *(const u64*)&xs[o*RS3 + jB + 2]);

        float2 f0 = unpack2(r0), f1 = unpack2(r1);
        float2 f2 = unpack2(r2), f3 = unpack2(r3);
        *(float4*)&out[obase + (long)o*(T_*V_) + jA] = make_float4(f0.x, f0.y, f1.x, f1.y);
        *(float4*)&out[obase + (long)o*(T_*V_) + jB] = make_float4(f2.x, f2.y, f3.x, f3.y);
    }
}

// ---------------------------------------------------------------------------
extern "C" void kernel_launch(void* const* d_in, const int* in_sizes, int n_in,
                              void* d_out, int out_size)
{
    const float* x     = (const float*)d_in[0];
    const float* Abase = (const float*)d_in[1];
    const float* PA    = (const float*)d_in[2];
    const float* Wa    = (const float*)d_in[3];
    const float* ba    = (const float*)d_in[4];
    const float* Wb    = (const float*)d_in[5];
    const float* bb    = (const float*)d_in[6];
    const float* Wd    = (const float*)d_in[7];
    const float* bd    = (const float*)d_in[8];
    const float* gamma = (const float*)d_in[9];
    const float* beta  = (const float*)d_in[10];
    float* out = (float*)d_out;

    cudaFuncSetAttribute(k1_att_partial, cudaFuncAttributeMaxDynamicSharedMemorySize, SMEM1_BYTES);
    cudaFuncSetAttribute(k3_out,        cudaFuncAttributeMaxDynamicSharedMemorySize, SMEM3_BYTES);

    dim3 g1(NCH, N_);
    k1_att_partial<<<g1, 256, SMEM1_BYTES>>>(x, Wa, ba, Wb, bb);

    k2_softmax<<<N_*S_, 256>>>(Abase, PA);

    dim3 g3(NCH3, N_);
    k3_out<<<g3, 512, SMEM3_BYTES>>>(x, Wd, bd, gamma, beta, out);
}

// round 2
// speedup vs baseline: 1.1508x; 1.1508x over previous
#include <cuda_runtime.h>

// Problem dims
#define N_   128
#define C_   64
#define T_   288
#define V_   16
#define S_   3
#define IC_  16
#define KCT  (IC_*T_)      // 4608
#define TV_  (T_*V_)       // 4608

// Kernel 1 tiling
#define TT1  8
#define J1   (TT1*V_)      // 128
#define NCH  (T_/TT1)      // 36

// Kernel 3 tiling
#define TT3  16
#define J3   (TT3*V_)      // 256
#define NCH3 (T_/TT3)      // 18
#define RS3  258           // xs/zs row stride: bank stride 2 for column access

// Scratch (no cudaMalloc allowed)
__device__ float g_partial[(long)N_*NCH*S_*V_*V_];   // [n][ch][s][v*16+w]
__device__ float g_att[(long)N_*S_*V_*V_];           // [n][s][v*16+w]
__device__ float g_WaT[S_*C_*IC_];                   // [s][c][i]
__device__ float g_WbT[S_*C_*IC_];
__device__ float g_WdT[S_*C_*C_];                    // [s][c][o]

typedef unsigned long long u64;

__device__ __forceinline__ u64 splat2(float x) {
    u64 r; asm("mov.b64 %0, {%1, %1};" : "=l"(r) : "f"(x)); return r;
}
__device__ __forceinline__ void fma2(u64& d, u64 a, u64 b) {
    asm("fma.rn.f32x2 %0, %1, %2, %0;" : "+l"(d) : "l"(a), "l"(b));
}
__device__ __forceinline__ u64 add2(u64 a, u64 b) {
    u64 r; asm("add.rn.f32x2 %0, %1, %2;" : "=l"(r) : "l"(a), "l"(b)); return r;
}
__device__ __forceinline__ float2 unpack2(u64 a) {
    float2 r; asm("mov.b64 {%0, %1}, %2;" : "=f"(r.x), "=f"(r.y) : "l"(a)); return r;
}

// ---------------------------------------------------------------------------
// Kernel 0: pre-transpose weights so all later staging is coalesced and
// conflict-free. One block; trivial cost.
// ---------------------------------------------------------------------------
extern "C" __global__ void k0_transpose(const float* __restrict__ Wa,
                                        const float* __restrict__ Wb,
                                        const float* __restrict__ Wd)
{
    const int tid = threadIdx.x;
    for (int idx = tid; idx < S_*C_*IC_; idx += 256) {
        int i = idx & 15, c = (idx >> 4) & 63, s = idx >> 10;
        g_WaT[idx] = Wa[(s*16 + i)*64 + c];
        g_WbT[idx] = Wb[(s*16 + i)*64 + c];
    }
    for (int idx = tid; idx < S_*C_*C_; idx += 256) {
        int o = idx & 63, c = (idx >> 6) & 63, s = idx >> 12;
        g_WdT[idx] = Wd[(s*64 + o)*64 + c];
    }
}

// ---------------------------------------------------------------------------
// Kernel 1: att logit partials. Grid (NCH, N), 256 threads, occ 2.
// phase1: fa/fb tiles [16][128] via f32x2, conflict-free layouts.
// phase2: partial[v][w] += fa[.,v]*fb[.,w] with u64 loads (1 phase each).
// ---------------------------------------------------------------------------
#define SM1_XS   0
#define SM1_FA   8192
#define SM1_FB   10240
#define SM1_WAT  12288
#define SM1_WBT  15360
#define SM1_ATTP 18432
#define SMEM1_BYTES ((18432 + 1024)*4)   // 77824 B

extern "C" __global__ void __launch_bounds__(256, 2)
k1_att_partial(const float* __restrict__ x,
               const float* __restrict__ ba, const float* __restrict__ bb)
{
    extern __shared__ float sm[];
    float* xs   = sm + SM1_XS;    // [64][128]
    float* fas  = sm + SM1_FA;    // [16][128]
    float* fbs  = sm + SM1_FB;    // [16][128]
    float* Wat  = sm + SM1_WAT;   // [s][c][i]
    float* Wbt  = sm + SM1_WBT;
    float* attp = sm + SM1_ATTP;  // [4][256]

    const int ch  = blockIdx.x;
    const int n   = blockIdx.y;
    const int tid = threadIdx.x;
    const int lane = tid & 31, wrp = tid >> 5;

    const long xbase = (long)n*C_*TV_ + (long)(ch*TT1)*V_;
    // stage x as u64 (lane-consecutive both sides)
    for (int idx = tid; idx < 4096; idx += 256) {
        int c = idx >> 6, jp = (idx & 63)*2;
        *(u64*)&xs[c*128 + jp] = *(const u64*)&x[xbase + (long)c*TV_ + jp];
    }
    for (int idx = tid; idx < S_*C_*IC_; idx += 256) {
        Wat[idx] = g_WaT[idx];
        Wbt[idx] = g_WbT[idx];
    }
    __syncthreads();

    // phase1 mapping: 4 i x one u64 j
    const int i0   = (wrp & 3)*4;
    const int jcol = 64*(wrp >> 2) + 2*lane;
    // phase2 mapping
    const int q  = tid >> 6;
    const int pv = (tid >> 3) & 7;
    const int pw = tid & 7;

    for (int s = 0; s < S_; s++) {
        // ---- phase 1 ----
        u64 aA[4], aB[4];
        #pragma unroll
        for (int ii = 0; ii < 4; ii++) { aA[ii] = 0ull; aB[ii] = 0ull; }
        const float* wap = &Wat[s*1024];
        const float* wbp = &Wbt[s*1024];
        #pragma unroll 4
        for (int c = 0; c < 64; c++) {
            u64 xq = *(const u64*)&xs[c*128 + jcol];       // 2 phases
            float4 wa4 = *(const float4*)&wap[c*16 + i0];  // broadcast
            float4 wb4 = *(const float4*)&wbp[c*16 + i0];  // broadcast
            fma2(aA[0], splat2(wa4.x), xq);
            fma2(aA[1], splat2(wa4.y), xq);
            fma2(aA[2], splat2(wa4.z), xq);
            fma2(aA[3], splat2(wa4.w), xq);
            fma2(aB[0], splat2(wb4.x), xq);
            fma2(aB[1], splat2(wb4.y), xq);
            fma2(aB[2], splat2(wb4.z), xq);
            fma2(aB[3], splat2(wb4.w), xq);
        }
        #pragma unroll
        for (int ii = 0; ii < 4; ii++) {
            u64 fav = add2(aA[ii], splat2(ba[s*16 + i0 + ii]));
            u64 fbv = add2(aB[ii], splat2(bb[s*16 + i0 + ii]));
            *(u64*)&fas[(i0 + ii)*128 + jcol] = fav;
            *(u64*)&fbs[(i0 + ii)*128 + jcol] = fbv;
        }
        __syncthreads();

        // ---- phase 2: 2v x 2w tile, term-split 4 ways ----
        u64 acc0 = 0ull, acc1 = 0ull;
        #pragma unroll 8
        for (int r = 0; r < 32; r++) {
            int term = q*32 + r;                          // (i,t') combined
            u64 fp = *(const u64*)&fas[term*16 + 2*pv];   // 1 phase
            u64 gp = *(const u64*)&fbs[term*16 + 2*pw];   // 1 phase
            float2 f2 = unpack2(fp);
            fma2(acc0, splat2(f2.x), gp);
            fma2(acc1, splat2(f2.y), gp);
        }
        *(u64*)&attp[q*256 + (2*pv  )*16 + 2*pw] = acc0;
        *(u64*)&attp[q*256 + (2*pv+1)*16 + 2*pw] = acc1;
        __syncthreads();

        float red = attp[tid] + attp[256 + tid] + attp[512 + tid] + attp[768 + tid];
        g_partial[(((long)n*NCH + ch)*S_ + s)*256 + tid] = red;
        // fas reads all precede the sync above; safe to rewrite next iter
    }
}

// ---------------------------------------------------------------------------
// Kernel 2: reduce chunks, /K, softmax over v, + (A_base + PA).
// ---------------------------------------------------------------------------
extern "C" __global__ void k2_softmax(const float* __restrict__ Abase,
                                      const float* __restrict__ PA)
{
    const int b = blockIdx.x;          // n*3 + s
    const int n = b / S_, s = b % S_;
    const int tid = threadIdx.x;       // v*16 + w
    const int w = tid & 15;

    __shared__ float sv[256];
    __shared__ float se[256];

    float sum = 0.f;
    const float* p = &g_partial[((long)n*NCH)*S_*256 + s*256 + tid];
    for (int chv = 0; chv < NCH; chv++) sum += p[(long)chv * (S_*256)];
    float val = sum * (1.0f / (float)KCT);

    sv[tid] = val;
    __syncthreads();
    float m = -1e30f;
    #pragma unroll
    for (int vv = 0; vv < 16; vv++) m = fmaxf(m, sv[vv*16 + w]);
    float e = expf(val - m);
    se[tid] = e;
    __syncthreads();
    float ss = 0.f;
    #pragma unroll
    for (int vv = 0; vv < 16; vv++) ss += se[vv*16 + w];

    float a = e / ss + Abase[s*256 + tid] + PA[s*256 + tid];
    g_att[(long)b*256 + tid] = a;
}

// ---------------------------------------------------------------------------
// Kernel 3: z = x @ att (smem), y = sum_s Wd_s @ z_s, BN+bias+residual.
// Grid (NCH3, N), 512 threads. All hot LDS either lane-consecutive or
// broadcast; column (splat) access 2-way max via RS3=258.
// ---------------------------------------------------------------------------
#define SM3_XS   0
#define SM3_ZS   16512
#define SM3_WDT  33024
#define SM3_ATT  45312
#define SMEM3_BYTES ((45312 + 768)*4)   // 184320 B

extern "C" __global__ void __launch_bounds__(512, 1)
k3_out(const float* __restrict__ x,
       const float* __restrict__ bd, const float* __restrict__ gamma,
       const float* __restrict__ beta, float* __restrict__ out)
{
    extern __shared__ float sm[];
    float* xs   = sm + SM3_XS;    // [64][RS3]
    float* zs   = sm + SM3_ZS;    // [64][RS3]
    float* Wdt  = sm + SM3_WDT;   // [s][c][o]  (pre-transposed)
    float* atts = sm + SM3_ATT;   // [s][v][w]

    const int ch  = blockIdx.x;
    const int n   = blockIdx.y;
    const int tid = threadIdx.x;
    const int lane = tid & 31, wrp = tid >> 5;

    const long xbase = (long)n*C_*TV_ + (long)(ch*TT3)*V_;
    for (int idx = tid; idx < 64*128; idx += 512) {
        int c = idx >> 7, jp = (idx & 127)*2;
        *(u64*)&xs[c*RS3 + jp] = *(const u64*)&x[xbase + (long)c*TV_ + jp];
    }
    for (int idx = tid; idx < S_*C_*C_; idx += 512) Wdt[idx] = g_WdT[idx];
    for (int idx = tid; idx < S_*256;   idx += 512) atts[idx] = g_att[(long)n*S_*256 + idx];
    __syncthreads();

    // z mapping: thread owns rows {lane, lane+32} at t' = wrp
    const int ca = lane, cb = lane + 32;
    const int jz = wrp * 16;
    // y mapping: 8 o x 2 u64 j
    const int o0 = (tid >> 6) * 8;
    const int jA = 64*((wrp) & 1) + 2*lane;
    const int jB = jA + 128;

    u64 yacc[16];
    #pragma unroll
    for (int k = 0; k < 16; k++) yacc[k] = 0ull;

    for (int s = 0; s < S_; s++) {
        // ---- z tile ----
        u64 zacc[16];
        #pragma unroll
        for (int k = 0; k < 16; k++) zacc[k] = 0ull;
        const float* ap = &atts[s*256];
        #pragma unroll
        for (int v = 0; v < 16; v++) {
            ulonglong2 arq0 = *(const ulonglong2*)&ap[v*16 +  0];  // broadcast
            ulonglong2 arq1 = *(const ulonglong2*)&ap[v*16 +  4];
            ulonglong2 arq2 = *(const ulonglong2*)&ap[v*16 +  8];
            ulonglong2 arq3 = *(const ulonglong2*)&ap[v*16 + 12];
            u64 xa = splat2(xs[ca*RS3 + jz + v]);   // 2-way conflict max
            u64 xb = splat2(xs[cb*RS3 + jz + v]);
            fma2(zacc[0], xa, arq0.x); fma2(zacc[1], xa, arq0.y);
            fma2(zacc[2], xa, arq1.x); fma2(zacc[3], xa, arq1.y);
            fma2(zacc[4], xa, arq2.x); fma2(zacc[5], xa, arq2.y);
            fma2(zacc[6], xa, arq3.x); fma2(zacc[7], xa, arq3.y);
            fma2(zacc[ 8], xb, arq0.x); fma2(zacc[ 9], xb, arq0.y);
            fma2(zacc[10], xb, arq1.x); fma2(zacc[11], xb, arq1.y);
            fma2(zacc[12], xb, arq2.x); fma2(zacc[13], xb, arq2.y);
            fma2(zacc[14], xb, arq3.x); fma2(zacc[15], xb, arq3.y);
        }
        #pragma unroll
        for (int p = 0; p < 8; p++) {
            *(u64*)&zs[ca*RS3 + jz + 2*p] = zacc[p];
            *(u64*)&zs[cb*RS3 + jz + 2*p] = zacc[8 + p];
        }
        __syncthreads();

        // ---- y += Wd_s @ z_s ----
        const float* wp = &Wdt[s*4096];
        #pragma unroll 4
        for (int c = 0; c < 64; c++) {
            float4 wA = *(const float4*)&wp[c*64 + o0];      // broadcast
            float4 wB = *(const float4*)&wp[c*64 + o0 + 4];  // broadcast
            const float* zr = &zs[c*RS3];
            u64 z0 = *(const u64*)&zr[jA];                   // lane-consecutive
            u64 z1 = *(const u64*)&zr[jB];
            u64 w0 = splat2(wA.x), w1 = splat2(wA.y), w2 = splat2(wA.z), w3 = splat2(wA.w);
            u64 w4 = splat2(wB.x), w5 = splat2(wB.y), w6 = splat2(wB.z), w7 = splat2(wB.w);
            fma2(yacc[ 0], w0, z0); fma2(yacc[ 1], w0, z1);
            fma2(yacc[ 2], w1, z0); fma2(yacc[ 3], w1, z1);
            fma2(yacc[ 4], w2, z0); fma2(yacc[ 5], w2, z1);
            fma2(yacc[ 6], w3, z0); fma2(yacc[ 7], w3, z1);
            fma2(yacc[ 8], w4, z0); fma2(yacc[ 9], w4, z1);
            fma2(yacc[10], w5, z0); fma2(yacc[11], w5, z1);
            fma2(yacc[12], w6, z0); fma2(yacc[13], w6, z1);
            fma2(yacc[14], w7, z0); fma2(yacc[15], w7, z1);
        }
        __syncthreads();
    }

    // ---- epilogue: BN scale/shift + bd sum + residual ----
    const float rsv = rsqrtf(1.0f + 1e-5f);
    const long obase = xbase;
    #pragma unroll
    for (int oo = 0; oo < 8; oo++) {
        int o = o0 + oo;
        float sc = gamma[o] * rsv;
        float bi = beta[o] + bd[o] + bd[64 + o] + bd[128 + o];
        u64 sc2 = splat2(sc), bi2 = splat2(bi);

        u64 r0 = bi2, r1 = bi2;
        fma2(r0, yacc[2*oo    ], sc2);
        fma2(r1, yacc[2*oo + 1], sc2);
        r0 = add2(r0, *(const u64*)&xs[o*RS3 + jA]);
        r1 = add2(r1, *(const u64*)&xs[o*RS3 + jB]);

        *(u64*)&out[obase + (long)o*TV_ + jA] = r0;
        *(u64*)&out[obase + (long)o*TV_ + jB] = r1;
    }
}

// ---------------------------------------------------------------------------
extern "C" void kernel_launch(void* const* d_in, const int* in_sizes, int n_in,
                              void* d_out, int out_size)
{
    const float* x     = (const float*)d_in[0];
    const float* Abase = (const float*)d_in[1];
    const float* PA    = (const float*)d_in[2];
    const float* Wa    = (const float*)d_in[3];
    const float* ba    = (const float*)d_in[4];
    const float* Wb    = (const float*)d_in[5];
    const float* bb    = (const float*)d_in[6];
    const float* Wd    = (const float*)d_in[7];
    const float* bd    = (const float*)d_in[8];
    const float* gamma = (const float*)d_in[9];
    const float* beta  = (const float*)d_in[10];
    float* out = (float*)d_out;

    cudaFuncSetAttribute(k1_att_partial, cudaFuncAttributeMaxDynamicSharedMemorySize, SMEM1_BYTES);
    cudaFuncSetAttribute(k3_out,        cudaFuncAttributeMaxDynamicSharedMemorySize, SMEM3_BYTES);

    k0_transpose<<<1, 256>>>(Wa, Wb, Wd);

    dim3 g1(NCH, N_);
    k1_att_partial<<<g1, 256, SMEM1_BYTES>>>(x, ba, bb);

    k2_softmax<<<N_*S_, 256>>>(Abase, PA);

    dim3 g3(NCH3, N_);
    k3_out<<<g3, 512, SMEM3_BYTES>>>(x, bd, gamma, beta, out);
}